// round 6
// baseline (speedup 1.0000x reference)
#include <cuda.h>
#include <cuda_runtime.h>
#include <cuda_fp16.h>
#include <cstdint>

// ============================================================================
// Problem constants
// ============================================================================
static constexpr int MT = 8192;   // batch*seq = 4*2048
static constexpr int NT = 4096;   // out features
static constexpr int KT = 4096;   // in features

static constexpr int BM = 128;
static constexpr int BN = 128;
static constexpr int BK = 64;     // fp16 elems per stage (128B rows, SW128 atom)
static constexpr int NS = 4;      // pipeline stages
static constexpr int KIT = KT / BK;  // 64

static constexpr int A_STAGE = BM * 128;   // 16384 B
static constexpr int B_STAGE = BN * 128;   // 16384 B
static constexpr int OFF_A = 1024;
static constexpr int OFF_B = OFF_A + NS * A_STAGE;           // 66560 (1024-aligned)
static constexpr int SMEM_BYTES = OFF_B + NS * B_STAGE;      // 132096

// Scratch (device globals — allocation-free per harness rules)
__device__ __align__(1024) __half g_Xh[(size_t)MT * KT];   // 64 MB
__device__ __align__(1024) __half g_Wh[(size_t)NT * KT];   // 32 MB

// ============================================================================
// PTX helpers (ALL base-ISA: sm_90 or earlier — no 'a'-gated features)
// ============================================================================
__device__ __forceinline__ uint32_t smem_u32(const void* p) {
    uint32_t a;
    asm("{ .reg .u64 t; cvta.to.shared.u64 t, %1; cvt.u32.u64 %0, t; }"
        : "=r"(a) : "l"(p));
    return a;
}

__device__ __forceinline__ uint32_t elect_one_pred() {
    uint32_t pred;
    asm volatile(
        "{\n\t.reg .pred p;\n\t"
        "elect.sync _|p, 0xFFFFFFFF;\n\t"
        "selp.b32 %0, 1, 0, p;\n\t}"
        : "=r"(pred));
    return pred;
}

#define MBARRIER_INIT(addr, cnt) \
    asm volatile("mbarrier.init.shared.b64 [%0], %1;" \
                 :: "r"((uint32_t)(addr)), "r"((uint32_t)(cnt)) : "memory")

#define MBARRIER_EXPECT_TX(addr, bytes) \
    asm volatile("mbarrier.arrive.expect_tx.shared.b64 _, [%0], %1;" \
                 :: "r"((uint32_t)(addr)), "r"((uint32_t)(bytes)) : "memory")

#define MBARRIER_ARRIVE(addr) \
    asm volatile("mbarrier.arrive.shared.b64 _, [%0];" \
                 :: "r"((uint32_t)(addr)) : "memory")

// Passes when the barrier's phase bit != parity argument.
#define MBARRIER_WAIT_PARITY(mbar_smem_addr, phase_parity) do { \
    uint32_t _mbar = (uint32_t)(mbar_smem_addr); \
    uint32_t _parity = (uint32_t)(phase_parity); \
    uint32_t _done; \
    asm volatile( \
        "{\n\t.reg .pred p;\n\t" \
        "mbarrier.try_wait.parity.acquire.cta.shared::cta.b64 p, [%1], %2;\n\t" \
        "selp.b32 %0, 1, 0, p;\n\t}" \
        : "=r"(_done) : "r"(_mbar), "r"(_parity) : "memory"); \
    if (!_done) { \
        asm volatile( \
            "{\n\t.reg .pred P1;\n\t" \
            "WAIT_LOOP_%=:\n\t" \
            "mbarrier.try_wait.parity.acquire.cta.shared::cta.b64 P1, [%0], %1, 0x989680;\n\t" \
            "@P1 bra.uni WAIT_DONE_%=;\n\t" \
            "bra.uni WAIT_LOOP_%=;\n\t" \
            "WAIT_DONE_%=:\n\t}" \
            :: "r"(_mbar), "r"(_parity) : "memory"); \
    } \
} while (0)

__device__ __forceinline__ void tma_load_2d(uint32_t smem_addr, const CUtensorMap* map,
                                            int cx, int cy, uint32_t mbar) {
    asm volatile(
        "cp.async.bulk.tensor.2d.shared::cta.global.tile.mbarrier::complete_tx::bytes "
        "[%0], [%1, {%2, %3}], [%4];"
        :: "r"(smem_addr), "l"(map), "r"(cx), "r"(cy), "r"(mbar) : "memory");
}

__device__ __forceinline__ void ldmatrix_x4(uint32_t& r0, uint32_t& r1,
                                            uint32_t& r2, uint32_t& r3, uint32_t addr) {
    asm volatile("ldmatrix.sync.aligned.m8n8.x4.shared.b16 {%0, %1, %2, %3}, [%4];"
                 : "=r"(r0), "=r"(r1), "=r"(r2), "=r"(r3) : "r"(addr));
}

__device__ __forceinline__ uint32_t lds_b32(uint32_t addr) {
    uint32_t v;
    asm volatile("ld.shared.b32 %0, [%1];" : "=r"(v) : "r"(addr));
    return v;
}

__device__ __forceinline__ void mma_16816(float* c, const uint32_t* a, const uint32_t* b) {
    asm volatile(
        "mma.sync.aligned.m16n8k16.row.col.f32.f16.f16.f32 "
        "{%0, %1, %2, %3}, {%4, %5, %6, %7}, {%8, %9}, {%0, %1, %2, %3};"
        : "+f"(c[0]), "+f"(c[1]), "+f"(c[2]), "+f"(c[3])
        : "r"(a[0]), "r"(a[1]), "r"(a[2]), "r"(a[3]), "r"(b[0]), "r"(b[1]));
}

// SW128 swizzle for 128B-row tiles: only the row part feeds the XOR.
__device__ __forceinline__ uint32_t sw128(uint32_t row, uint32_t byte_in_row) {
    return row * 128u + (byte_in_row ^ ((row & 7u) << 4));
}

// ============================================================================
// Prep kernels
// ============================================================================
__global__ void convert_x_kernel(const float4* __restrict__ x, uint2* __restrict__ xh, int n4) {
    int i = blockIdx.x * blockDim.x + threadIdx.x;
    if (i < n4) {
        float4 v = x[i];
        __half2 a = __floats2half2_rn(v.x, v.y);
        __half2 b = __floats2half2_rn(v.z, v.w);
        uint2 o;
        o.x = *reinterpret_cast<uint32_t*>(&a);
        o.y = *reinterpret_cast<uint32_t*>(&b);
        xh[i] = o;
    }
}

__global__ void dequant_w_kernel(const int4* __restrict__ wp, const float2* __restrict__ par,
                                 uint4* __restrict__ wh, int n4) {
    int t = blockIdx.x * blockDim.x + threadIdx.x;
    if (t < n4) {
        int4 p = wp[t];
        int g = t >> 5;  // 32 int4s (=128 int32s) per group of 256 values
        float2 sz = par[g];
        float s = sz.x, z = sz.y;
        uint4 o;
        {
            __half2 h = __floats2half2_rn((float)(p.x & 15) * s + z,
                                          (float)((p.x >> 4) & 15) * s + z);
            o.x = *reinterpret_cast<uint32_t*>(&h);
        }
        {
            __half2 h = __floats2half2_rn((float)(p.y & 15) * s + z,
                                          (float)((p.y >> 4) & 15) * s + z);
            o.y = *reinterpret_cast<uint32_t*>(&h);
        }
        {
            __half2 h = __floats2half2_rn((float)(p.z & 15) * s + z,
                                          (float)((p.z >> 4) & 15) * s + z);
            o.z = *reinterpret_cast<uint32_t*>(&h);
        }
        {
            __half2 h = __floats2half2_rn((float)(p.w & 15) * s + z,
                                          (float)((p.w >> 4) & 15) * s + z);
            o.w = *reinterpret_cast<uint32_t*>(&h);
        }
        wh[t] = o;
    }
}

// ============================================================================
// GEMM: D[8192,4096] = Xh @ Wh^T
// TMA + mbarrier 4-stage pipeline, mma.sync.m16n8k16 consumers (base ISA only).
// 8 compute warps (warp tile 64x32, 2x4 grid) + 1 TMA producer warp.
// ============================================================================
__global__ void __launch_bounds__(288, 1)
gemm_f16_kernel(const __grid_constant__ CUtensorMap tma_a,
                const __grid_constant__ CUtensorMap tma_b,
                float* __restrict__ out) {
    extern __shared__ char smem[];
    const uint32_t sb = smem_u32(smem);
    const int tid = threadIdx.x;
    const int wid = tid >> 5;
    const int lid = tid & 31;
    const int n0 = blockIdx.x * BN;
    const int m0 = blockIdx.y * BM;

    // Barriers: full[s] at sb+64+16s (tx-based), empty[s] at sb+192+16s (count 8)
    const uint32_t FULLB  = sb + 64;
    const uint32_t EMPTYB = sb + 192;

    if (tid == 0) {
        #pragma unroll
        for (int s = 0; s < NS; s++) {
            MBARRIER_INIT(FULLB + 16 * s, 1);
            MBARRIER_INIT(EMPTYB + 16 * s, 8);   // lane0 of each of 8 compute warps
        }
    }
    __syncthreads();

    if (wid == 8) {
        // ------------------- TMA producer warp -------------------
        if (elect_one_pred()) {
            for (int i = 0; i < KIT; i++) {
                const int s = i & (NS - 1);
                const int ph = (i >> 2) & 1;
                // first NS passes free (bit=0 != parity=1)
                MBARRIER_WAIT_PARITY(EMPTYB + 16 * s, 1 ^ ph);
                MBARRIER_EXPECT_TX(FULLB + 16 * s, (uint32_t)(A_STAGE + B_STAGE));
                tma_load_2d(sb + OFF_A + s * A_STAGE, &tma_a, i * BK, m0, FULLB + 16 * s);
                tma_load_2d(sb + OFF_B + s * B_STAGE, &tma_b, i * BK, n0, FULLB + 16 * s);
            }
        }
    } else {
        // ------------------- Compute warps (8): warp tile 64(m) x 32(n) ---
        const int cm = (wid & 1) * 64;    // m offset within CTA tile
        const int cn = (wid >> 1) * 32;   // n offset within CTA tile

        const int g = lid >> 2;           // mma group id (row within 8)
        const int t = lid & 3;            // thread-in-group

        // ldmatrix.x4 per-lane row/col for A fragments:
        // matrices: m0=(r0-7,kb+0) m1=(r8-15,kb+0) m2=(r0-7,kb+16) m3=(r8-15,kb+16)
        const int a_row_in16 = ((lid >> 3) & 1) * 8 + (lid & 7);
        const int a_kb_extra = (lid >> 4) * 16;

        float acc[4][4][4];               // [mt][nt][reg]
        #pragma unroll
        for (int mt = 0; mt < 4; mt++)
            #pragma unroll
            for (int nt = 0; nt < 4; nt++)
                #pragma unroll
                for (int r = 0; r < 4; r++) acc[mt][nt][r] = 0.0f;

        for (int i = 0; i < KIT; i++) {
            const int s = i & (NS - 1);
            const int ph = (i >> 2) & 1;
            MBARRIER_WAIT_PARITY(FULLB + 16 * s, ph);

            const uint32_t Ab = sb + OFF_A + s * A_STAGE;
            const uint32_t Bb = sb + OFF_B + s * B_STAGE;

            #pragma unroll
            for (int ks = 0; ks < BK / 16; ks++) {
                // A fragments: 4 m16 tiles
                uint32_t af[4][4];
                #pragma unroll
                for (int mt = 0; mt < 4; mt++) {
                    uint32_t row = (uint32_t)(cm + mt * 16 + a_row_in16);
                    uint32_t addr = Ab + sw128(row, (uint32_t)(ks * 32 + a_kb_extra));
                    ldmatrix_x4(af[mt][0], af[mt][1], af[mt][2], af[mt][3], addr);
                }
                // B fragments: 4 n8 tiles, k-contiguous in [n][k] storage
                uint32_t bf[4][2];
                #pragma unroll
                for (int nt = 0; nt < 4; nt++) {
                    uint32_t row = (uint32_t)(cn + nt * 8 + g);
                    bf[nt][0] = lds_b32(Bb + sw128(row, (uint32_t)(ks * 32 + 4 * t)));
                    bf[nt][1] = lds_b32(Bb + sw128(row, (uint32_t)(ks * 32 + 4 * t + 16)));
                }
                #pragma unroll
                for (int mt = 0; mt < 4; mt++)
                    #pragma unroll
                    for (int nt = 0; nt < 4; nt++)
                        mma_16816(acc[mt][nt], af[mt], bf[nt]);
            }

            __syncwarp();
            if (lid == 0) MBARRIER_ARRIVE(EMPTYB + 16 * s);
        }

        // ------------------- Epilogue: regs -> gmem fp32 -------------------
        #pragma unroll
        for (int mt = 0; mt < 4; mt++) {
            const int row = m0 + cm + mt * 16 + g;
            float* r0p = out + (size_t)row * NT + (n0 + cn);
            float* r8p = out + (size_t)(row + 8) * NT + (n0 + cn);
            #pragma unroll
            for (int nt = 0; nt < 4; nt++) {
                const int col = nt * 8 + 2 * t;
                *reinterpret_cast<float2*>(r0p + col) =
                    make_float2(acc[mt][nt][0], acc[mt][nt][1]);
                *reinterpret_cast<float2*>(r8p + col) =
                    make_float2(acc[mt][nt][2], acc[mt][nt][3]);
            }
        }
    }
}

// ============================================================================
// Host launcher
// ============================================================================
typedef CUresult (*PFN_encodeTiled_t)(
    CUtensorMap*, CUtensorMapDataType, cuuint32_t, void*,
    const cuuint64_t*, const cuuint64_t*, const cuuint32_t*, const cuuint32_t*,
    CUtensorMapInterleave, CUtensorMapSwizzle, CUtensorMapL2promotion,
    CUtensorMapFloatOOBfill);

static void encode_fp16_2d(PFN_encodeTiled_t fn, CUtensorMap* map, void* ptr,
                           uint64_t d0, uint64_t d1, uint32_t b0, uint32_t b1) {
    cuuint64_t dims[2] = {d0, d1};
    cuuint64_t strides[1] = {d0 * 2};
    cuuint32_t box[2] = {b0, b1};
    cuuint32_t es[2] = {1, 1};
    fn(map, CU_TENSOR_MAP_DATA_TYPE_FLOAT16, 2, ptr, dims, strides, box, es,
       CU_TENSOR_MAP_INTERLEAVE_NONE, CU_TENSOR_MAP_SWIZZLE_128B,
       CU_TENSOR_MAP_L2_PROMOTION_L2_128B, CU_TENSOR_MAP_FLOAT_OOB_FILL_NONE);
}

extern "C" void kernel_launch(void* const* d_in, const int* in_sizes, int n_in,
                              void* d_out, int out_size) {
    const float* x = (const float*)d_in[0];
    const int* wp = (const int*)d_in[1];
    const float* par = (const float*)d_in[2];
    float* out = (float*)d_out;

    void* xh = nullptr;
    void* wh = nullptr;
    cudaGetSymbolAddress(&xh, g_Xh);
    cudaGetSymbolAddress(&wh, g_Wh);

    // 1) x fp32 -> fp16
    {
        int n4 = MT * KT / 4;  // 8388608
        convert_x_kernel<<<n4 / 256, 256>>>((const float4*)x, (uint2*)xh, n4);
    }
    // 2) dequantize 4-bit W -> fp16 [NT, KT] K-major
    {
        int n4 = NT * KT / 8;  // 2097152 int4s
        dequant_w_kernel<<<n4 / 256, 256>>>((const int4*)wp, (const float2*)par,
                                            (uint4*)wh, n4);
    }
    // 3) GEMM (TMA pipeline + mma.sync consumers)
    PFN_encodeTiled_t fn = nullptr;
    cudaDriverEntryPointQueryResult qr;
    cudaGetDriverEntryPoint("cuTensorMapEncodeTiled", (void**)&fn,
                            cudaEnableDefault, &qr);

    CUtensorMap ta, tb;
    encode_fp16_2d(fn, &ta, xh, (uint64_t)KT, (uint64_t)MT, (uint32_t)BK, (uint32_t)BM);
    encode_fp16_2d(fn, &tb, wh, (uint64_t)KT, (uint64_t)NT, (uint32_t)BK, (uint32_t)BN);

    cudaFuncSetAttribute(gemm_f16_kernel,
                         cudaFuncAttributeMaxDynamicSharedMemorySize, SMEM_BYTES);
    dim3 grid(NT / BN, MT / BM);  // (32, 64)
    gemm_f16_kernel<<<grid, 288, SMEM_BYTES>>>(ta, tb, out);
}

// round 11
// speedup vs baseline: 1.0288x; 1.0288x over previous
#include <cuda.h>
#include <cuda_runtime.h>
#include <cuda_fp16.h>
#include <cstdint>

// ============================================================================
// Problem constants
// ============================================================================
static constexpr int MT = 8192;   // batch*seq = 4*2048
static constexpr int NT = 4096;   // out features
static constexpr int KT = 4096;   // in features

static constexpr int BM = 128;
static constexpr int BN = 128;
static constexpr int BK = 64;     // fp16 elems per stage (128B rows, SW128 atom)
static constexpr int NS = 6;      // pipeline stages
static constexpr int KIT = KT / BK;  // 64

static constexpr int A_STAGE = BM * 128;   // 16384 B
static constexpr int B_STAGE = BN * 128;   // 16384 B
static constexpr int OFF_A = 1024;
static constexpr int OFF_B = OFF_A + NS * A_STAGE;           // 99328 (1024-aligned)
static constexpr int SMEM_BYTES = OFF_B + NS * B_STAGE;      // 197632

// Scratch (device globals — allocation-free per harness rules)
__device__ __align__(1024) __half g_Xh[(size_t)MT * KT];   // 64 MB
__device__ __align__(1024) __half g_Wh[(size_t)NT * KT];   // 32 MB

// ============================================================================
// PTX helpers (ALL base-ISA: sm_90 or earlier — no 'a'-gated features)
// ============================================================================
__device__ __forceinline__ uint32_t smem_u32(const void* p) {
    uint32_t a;
    asm("{ .reg .u64 t; cvta.to.shared.u64 t, %1; cvt.u32.u64 %0, t; }"
        : "=r"(a) : "l"(p));
    return a;
}

__device__ __forceinline__ uint32_t elect_one_pred() {
    uint32_t pred;
    asm volatile(
        "{\n\t.reg .pred p;\n\t"
        "elect.sync _|p, 0xFFFFFFFF;\n\t"
        "selp.b32 %0, 1, 0, p;\n\t}"
        : "=r"(pred));
    return pred;
}

#define MBARRIER_INIT(addr, cnt) \
    asm volatile("mbarrier.init.shared.b64 [%0], %1;" \
                 :: "r"((uint32_t)(addr)), "r"((uint32_t)(cnt)) : "memory")

#define MBARRIER_EXPECT_TX(addr, bytes) \
    asm volatile("mbarrier.arrive.expect_tx.shared.b64 _, [%0], %1;" \
                 :: "r"((uint32_t)(addr)), "r"((uint32_t)(bytes)) : "memory")

#define MBARRIER_ARRIVE(addr) \
    asm volatile("mbarrier.arrive.shared.b64 _, [%0];" \
                 :: "r"((uint32_t)(addr)) : "memory")

// Passes when the barrier's phase bit != parity argument.
#define MBARRIER_WAIT_PARITY(mbar_smem_addr, phase_parity) do { \
    uint32_t _mbar = (uint32_t)(mbar_smem_addr); \
    uint32_t _parity = (uint32_t)(phase_parity); \
    uint32_t _done; \
    asm volatile( \
        "{\n\t.reg .pred p;\n\t" \
        "mbarrier.try_wait.parity.acquire.cta.shared::cta.b64 p, [%1], %2;\n\t" \
        "selp.b32 %0, 1, 0, p;\n\t}" \
        : "=r"(_done) : "r"(_mbar), "r"(_parity) : "memory"); \
    if (!_done) { \
        asm volatile( \
            "{\n\t.reg .pred P1;\n\t" \
            "WAIT_LOOP_%=:\n\t" \
            "mbarrier.try_wait.parity.acquire.cta.shared::cta.b64 P1, [%0], %1, 0x989680;\n\t" \
            "@P1 bra.uni WAIT_DONE_%=;\n\t" \
            "bra.uni WAIT_LOOP_%=;\n\t" \
            "WAIT_DONE_%=:\n\t}" \
            :: "r"(_mbar), "r"(_parity) : "memory"); \
    } \
} while (0)

__device__ __forceinline__ void tma_load_2d(uint32_t smem_addr, const CUtensorMap* map,
                                            int cx, int cy, uint32_t mbar) {
    asm volatile(
        "cp.async.bulk.tensor.2d.shared::cta.global.tile.mbarrier::complete_tx::bytes "
        "[%0], [%1, {%2, %3}], [%4];"
        :: "r"(smem_addr), "l"(map), "r"(cx), "r"(cy), "r"(mbar) : "memory");
}

__device__ __forceinline__ void ldmatrix_x4(uint32_t& r0, uint32_t& r1,
                                            uint32_t& r2, uint32_t& r3, uint32_t addr) {
    asm volatile("ldmatrix.sync.aligned.m8n8.x4.shared.b16 {%0, %1, %2, %3}, [%4];"
                 : "=r"(r0), "=r"(r1), "=r"(r2), "=r"(r3) : "r"(addr));
}

__device__ __forceinline__ void mma_16816(float* c, const uint32_t* a, const uint32_t* b) {
    asm volatile(
        "mma.sync.aligned.m16n8k16.row.col.f32.f16.f16.f32 "
        "{%0, %1, %2, %3}, {%4, %5, %6, %7}, {%8, %9}, {%0, %1, %2, %3};"
        : "+f"(c[0]), "+f"(c[1]), "+f"(c[2]), "+f"(c[3])
        : "r"(a[0]), "r"(a[1]), "r"(a[2]), "r"(a[3]), "r"(b[0]), "r"(b[1]));
}

// SW128 swizzle for 128B-row tiles: only the row part feeds the XOR.
__device__ __forceinline__ uint32_t sw128(uint32_t row, uint32_t byte_in_row) {
    return row * 128u + (byte_in_row ^ ((row & 7u) << 4));
}

// ============================================================================
// Prep kernels
// ============================================================================
__global__ void convert_x_kernel(const float4* __restrict__ x, uint2* __restrict__ xh, int n4) {
    int i = blockIdx.x * blockDim.x + threadIdx.x;
    if (i < n4) {
        float4 v = x[i];
        __half2 a = __floats2half2_rn(v.x, v.y);
        __half2 b = __floats2half2_rn(v.z, v.w);
        uint2 o;
        o.x = *reinterpret_cast<uint32_t*>(&a);
        o.y = *reinterpret_cast<uint32_t*>(&b);
        xh[i] = o;
    }
}

__global__ void dequant_w_kernel(const int4* __restrict__ wp, const float2* __restrict__ par,
                                 uint4* __restrict__ wh, int n4) {
    int t = blockIdx.x * blockDim.x + threadIdx.x;
    if (t < n4) {
        int4 p = wp[t];
        int g = t >> 5;  // 32 int4s (=128 int32s) per group of 256 values
        float2 sz = par[g];
        float s = sz.x, z = sz.y;
        uint4 o;
        {
            __half2 h = __floats2half2_rn((float)(p.x & 15) * s + z,
                                          (float)((p.x >> 4) & 15) * s + z);
            o.x = *reinterpret_cast<uint32_t*>(&h);
        }
        {
            __half2 h = __floats2half2_rn((float)(p.y & 15) * s + z,
                                          (float)((p.y >> 4) & 15) * s + z);
            o.y = *reinterpret_cast<uint32_t*>(&h);
        }
        {
            __half2 h = __floats2half2_rn((float)(p.z & 15) * s + z,
                                          (float)((p.z >> 4) & 15) * s + z);
            o.z = *reinterpret_cast<uint32_t*>(&h);
        }
        {
            __half2 h = __floats2half2_rn((float)(p.w & 15) * s + z,
                                          (float)((p.w >> 4) & 15) * s + z);
            o.w = *reinterpret_cast<uint32_t*>(&h);
        }
        wh[t] = o;
    }
}

// ============================================================================
// GEMM: D[8192,4096] = Xh @ Wh^T
// TMA + mbarrier 6-stage pipeline, mma.sync.m16n8k16 consumers (base ISA only).
// 8 compute warps (warp tile 64x32, 2x4 grid) + 1 TMA producer warp.
// B fragments loaded via ldmatrix.x4 (2 per k16-slice instead of 8 lds.b32).
// ============================================================================
__global__ void __launch_bounds__(288, 1)
gemm_f16_kernel(const __grid_constant__ CUtensorMap tma_a,
                const __grid_constant__ CUtensorMap tma_b,
                float* __restrict__ out) {
    extern __shared__ char smem[];
    const uint32_t sb = smem_u32(smem);
    const int tid = threadIdx.x;
    const int wid = tid >> 5;
    const int lid = tid & 31;
    const int n0 = blockIdx.x * BN;
    const int m0 = blockIdx.y * BM;

    // Barriers: full[s] at sb+64+16s (tx-based), empty[s] at sb+256+16s (count 8)
    const uint32_t FULLB  = sb + 64;
    const uint32_t EMPTYB = sb + 256;

    if (tid == 0) {
        #pragma unroll
        for (int s = 0; s < NS; s++) {
            MBARRIER_INIT(FULLB + 16 * s, 1);
            MBARRIER_INIT(EMPTYB + 16 * s, 8);   // lane0 of each of 8 compute warps
        }
    }
    __syncthreads();

    if (wid == 8) {
        // ------------------- TMA producer warp -------------------
        if (elect_one_pred()) {
            int s = 0, ph = 0;
            for (int i = 0; i < KIT; i++) {
                // first NS passes free (bit=0 != parity=1)
                MBARRIER_WAIT_PARITY(EMPTYB + 16 * s, 1 ^ ph);
                MBARRIER_EXPECT_TX(FULLB + 16 * s, (uint32_t)(A_STAGE + B_STAGE));
                tma_load_2d(sb + OFF_A + s * A_STAGE, &tma_a, i * BK, m0, FULLB + 16 * s);
                tma_load_2d(sb + OFF_B + s * B_STAGE, &tma_b, i * BK, n0, FULLB + 16 * s);
                if (++s == NS) { s = 0; ph ^= 1; }
            }
        }
    } else {
        // ------------------- Compute warps (8): warp tile 64(m) x 32(n) ---
        const int cm = (wid & 1) * 64;    // m offset within CTA tile
        const int cn = (wid >> 1) * 32;   // n offset within CTA tile

        const int g = lid >> 2;           // mma group id
        const int t = lid & 3;            // thread-in-group

        // A ldmatrix.x4 per-lane row/byte:
        // matrices: m0=(r0-7,+0B) m1=(r8-15,+0B) m2=(r0-7,+16B) m3=(r8-15,+16B)
        const uint32_t a_row = (uint32_t)(cm + ((lid >> 3) & 1) * 8 + (lid & 7));
        const uint32_t a_byte = (uint32_t)((lid >> 4) * 16);

        // B ldmatrix.x4 per-lane row/byte (per pair of n8 tiles):
        // matrix0 = b0 of tile nt   (n rows +0..7,  k-bytes +0)
        // matrix1 = b1 of tile nt   (n rows +0..7,  k-bytes +16)
        // matrix2 = b0 of tile nt+1 (n rows +8..15, k-bytes +0)
        // matrix3 = b1 of tile nt+1 (n rows +8..15, k-bytes +16)
        const uint32_t b_row = (uint32_t)(cn + ((lid >> 4) & 1) * 8 + (lid & 7));
        const uint32_t b_byte = (uint32_t)(((lid >> 3) & 1) * 16);

        float acc[4][4][4];               // [mt][nt][reg]
        #pragma unroll
        for (int mt = 0; mt < 4; mt++)
            #pragma unroll
            for (int nt = 0; nt < 4; nt++)
                #pragma unroll
                for (int r = 0; r < 4; r++) acc[mt][nt][r] = 0.0f;

        int s = 0, ph = 0;
        for (int i = 0; i < KIT; i++) {
            MBARRIER_WAIT_PARITY(FULLB + 16 * s, ph);

            const uint32_t Ab = sb + OFF_A + s * A_STAGE;
            const uint32_t Bb = sb + OFF_B + s * B_STAGE;

            #pragma unroll
            for (int ks = 0; ks < BK / 16; ks++) {
                // A fragments: 4 m16 tiles (4 ldmatrix.x4)
                uint32_t af[4][4];
                #pragma unroll
                for (int mt = 0; mt < 4; mt++) {
                    uint32_t addr = Ab + sw128(a_row + mt * 16,
                                               (uint32_t)(ks * 32) + a_byte);
                    ldmatrix_x4(af[mt][0], af[mt][1], af[mt][2], af[mt][3], addr);
                }
                // B fragments: 4 n8 tiles (2 ldmatrix.x4, 2 tiles each)
                uint32_t bf[4][2];
                #pragma unroll
                for (int pr = 0; pr < 2; pr++) {
                    uint32_t addr = Bb + sw128(b_row + pr * 16,
                                               (uint32_t)(ks * 32) + b_byte);
                    ldmatrix_x4(bf[2 * pr][0], bf[2 * pr][1],
                                bf[2 * pr + 1][0], bf[2 * pr + 1][1], addr);
                }
                #pragma unroll
                for (int mt = 0; mt < 4; mt++)
                    #pragma unroll
                    for (int nt = 0; nt < 4; nt++)
                        mma_16816(acc[mt][nt], af[mt], bf[nt]);
            }

            __syncwarp();
            if (lid == 0) MBARRIER_ARRIVE(EMPTYB + 16 * s);
            if (++s == NS) { s = 0; ph ^= 1; }
        }

        // ------------------- Epilogue: regs -> gmem fp32 -------------------
        #pragma unroll
        for (int mt = 0; mt < 4; mt++) {
            const int row = m0 + cm + mt * 16 + g;
            float* r0p = out + (size_t)row * NT + (n0 + cn);
            float* r8p = out + (size_t)(row + 8) * NT + (n0 + cn);
            #pragma unroll
            for (int nt = 0; nt < 4; nt++) {
                const int col = nt * 8 + 2 * t;
                *reinterpret_cast<float2*>(r0p + col) =
                    make_float2(acc[mt][nt][0], acc[mt][nt][1]);
                *reinterpret_cast<float2*>(r8p + col) =
                    make_float2(acc[mt][nt][2], acc[mt][nt][3]);
            }
        }
    }
}

// ============================================================================
// Host launcher
// ============================================================================
typedef CUresult (*PFN_encodeTiled_t)(
    CUtensorMap*, CUtensorMapDataType, cuuint32_t, void*,
    const cuuint64_t*, const cuuint64_t*, const cuuint32_t*, const cuuint32_t*,
    CUtensorMapInterleave, CUtensorMapSwizzle, CUtensorMapL2promotion,
    CUtensorMapFloatOOBfill);

static void encode_fp16_2d(PFN_encodeTiled_t fn, CUtensorMap* map, void* ptr,
                           uint64_t d0, uint64_t d1, uint32_t b0, uint32_t b1) {
    cuuint64_t dims[2] = {d0, d1};
    cuuint64_t strides[1] = {d0 * 2};
    cuuint32_t box[2] = {b0, b1};
    cuuint32_t es[2] = {1, 1};
    fn(map, CU_TENSOR_MAP_DATA_TYPE_FLOAT16, 2, ptr, dims, strides, box, es,
       CU_TENSOR_MAP_INTERLEAVE_NONE, CU_TENSOR_MAP_SWIZZLE_128B,
       CU_TENSOR_MAP_L2_PROMOTION_L2_128B, CU_TENSOR_MAP_FLOAT_OOB_FILL_NONE);
}

extern "C" void kernel_launch(void* const* d_in, const int* in_sizes, int n_in,
                              void* d_out, int out_size) {
    const float* x = (const float*)d_in[0];
    const int* wp = (const int*)d_in[1];
    const float* par = (const float*)d_in[2];
    float* out = (float*)d_out;

    void* xh = nullptr;
    void* wh = nullptr;
    cudaGetSymbolAddress(&xh, g_Xh);
    cudaGetSymbolAddress(&wh, g_Wh);

    // 1) x fp32 -> fp16
    {
        int n4 = MT * KT / 4;  // 8388608
        convert_x_kernel<<<n4 / 256, 256>>>((const float4*)x, (uint2*)xh, n4);
    }
    // 2) dequantize 4-bit W -> fp16 [NT, KT] K-major
    {
        int n4 = NT * KT / 8;  // 2097152 int4s
        dequant_w_kernel<<<n4 / 256, 256>>>((const int4*)wp, (const float2*)par,
                                            (uint4*)wh, n4);
    }
    // 3) GEMM (TMA pipeline + mma.sync consumers)
    PFN_encodeTiled_t fn = nullptr;
    cudaDriverEntryPointQueryResult qr;
    cudaGetDriverEntryPoint("cuTensorMapEncodeTiled", (void**)&fn,
                            cudaEnableDefault, &qr);

    CUtensorMap ta, tb;
    encode_fp16_2d(fn, &ta, xh, (uint64_t)KT, (uint64_t)MT, (uint32_t)BK, (uint32_t)BM);
    encode_fp16_2d(fn, &tb, wh, (uint64_t)KT, (uint64_t)NT, (uint32_t)BK, (uint32_t)BN);

    cudaFuncSetAttribute(gemm_f16_kernel,
                         cudaFuncAttributeMaxDynamicSharedMemorySize, SMEM_BYTES);
    dim3 grid(NT / BN, MT / BM);  // (32, 64)
    gemm_f16_kernel<<<grid, 288, SMEM_BYTES>>>(ta, tb, out);
}